// round 11
// baseline (speedup 1.0000x reference)
#include <cuda_runtime.h>
#include <cuda_fp16.h>
#include <cstdint>

typedef uint32_t u32;

#define TIN 128
#define TOUT 50
#define TSTEPS 178
#define NT 256
#define EPB 128                 // batch elements per CTA

#define STRIDE 144              // h-plane row stride (bytes): 16B-aligned rows (ldmatrix), conflict-free
#define PL (128 * STRIDE)       // one h plane = 18432 B
#define SM_WFC 0                // 64 float2 = 512 B
#define SM_EXT 512              // 2 buffers x 128 rows x 16 B = 4096
#define SM_AH  4608             // 2 x PL (h fp16 planes, double buffered)
#define SM_TOTAL (SM_AH + 2 * PL)   // 41472 B  (x2 CTAs = 83 KB/SM)

// ---------- primitives ----------
__device__ __forceinline__ float tanh_hw(float x){
    float r; asm("tanh.approx.f32 %0,%1;" : "=f"(r) : "f"(x)); return r;
}
__device__ __forceinline__ u32 tanh2u(u32 x){           // two tanh in one MUFU op
    u32 r; asm("tanh.approx.f16x2 %0,%1;" : "=r"(r) : "r"(x)); return r;
}
__device__ __forceinline__ u32 smem_u32(const void* p){
    u32 a; asm("{.reg .u64 t; cvta.to.shared.u64 t, %1; cvt.u32.u64 %0, t;}" : "=r"(a) : "l"(p));
    return a;
}
__device__ __forceinline__ u32 pack_f16(float a, float b){
    __half2 v = __floats2half2_rn(a, b);
    return *reinterpret_cast<u32*>(&v);
}
__device__ __forceinline__ __half2 u2h(u32 x){ return *reinterpret_cast<__half2*>(&x); }
__device__ __forceinline__ u32 h2u(__half2 x){ return *reinterpret_cast<u32*>(&x); }
__device__ __forceinline__ void split_hl(float v, float& hi, float& lo){
    hi = __half2float(__float2half_rn(v));
    lo = v - hi;
}

// mma.sync f16 (sm_80+ PTX, generic sm_103 target); non-volatile register dataflow
__device__ __forceinline__ void mma16816(float d[4], const u32 a[4], const u32 b[2]){
    asm("mma.sync.aligned.m16n8k16.row.col.f32.f16.f16.f32 "
        "{%0,%1,%2,%3},{%4,%5,%6,%7},{%8,%9},{%0,%1,%2,%3};"
        : "+f"(d[0]), "+f"(d[1]), "+f"(d[2]), "+f"(d[3])
        : "r"(a[0]), "r"(a[1]), "r"(a[2]), "r"(a[3]), "r"(b[0]), "r"(b[1]));
}
__device__ __forceinline__ void mma1688(float d[4], const u32 a[2], u32 b){
    asm("mma.sync.aligned.m16n8k8.row.col.f32.f16.f16.f32 "
        "{%0,%1,%2,%3},{%4,%5},{%6},{%0,%1,%2,%3};"
        : "+f"(d[0]), "+f"(d[1]), "+f"(d[2]), "+f"(d[3])
        : "r"(a[0]), "r"(a[1]), "r"(b));
}
__device__ __forceinline__ void ldmA(u32 a[4], u32 addr){
    asm volatile("ldmatrix.sync.aligned.m8n8.x4.shared.b16 {%0,%1,%2,%3}, [%4];"
                 : "=r"(a[0]), "=r"(a[1]), "=r"(a[2]), "=r"(a[3]) : "r"(addr));
}

// ---------- per-thread weight registers ----------
// warp w owns hidden dims 8w..8w+7; thread (g=lane>>2,q=lane&3): B col n = nt*64 + w*8 + g.
// fp16 single-term Whh; gates i,f,o (nt!=2) prescaled by 0.5 for tanh-based sigmoid.
struct Bregs { u32 bh[4][4][2]; u32 be[4]; };

__device__ void load_B(Bregs& B, const float* __restrict__ Whh, const float* __restrict__ Wih,
                       const float* __restrict__ bih, const float* __restrict__ bhh,
                       int w, int g, int q){
#pragma unroll
    for (int nt = 0; nt < 4; nt++){
        const float sc = (nt == 2) ? 1.0f : 0.5f;
        const int n = nt * 64 + w * 8 + g;
        const float* row = Whh + n * 64;
#pragma unroll
        for (int kt = 0; kt < 4; kt++){
            const int k0 = kt * 16 + 2 * q;
            B.bh[kt][nt][0] = pack_f16(row[k0]     * sc, row[k0 + 1] * sc);
            B.bh[kt][nt][1] = pack_f16(row[k0 + 8] * sc, row[k0 + 9] * sc);
        }
        // ext B rows: [W0h, W0l, W0h, W1h, W1l, W1h, bh, bl] (pairs with A_ext cols)
        float W0h,W0l,W1h,W1l,bsh,bsl;
        split_hl(Wih[n * 2]     * sc, W0h, W0l);
        split_hl(Wih[n * 2 + 1] * sc, W1h, W1l);
        split_hl((bih[n] + bhh[n]) * sc, bsh, bsl);
        u32 be;
        if      (q == 0) be = pack_f16(W0h, W0l);
        else if (q == 1) be = pack_f16(W0h, W1h);
        else if (q == 2) be = pack_f16(W1l, W1h);
        else             be = pack_f16(bsh, bsl);
        B.be[nt] = be;
    }
}

// A_ext row m (16B): cols [x0h,x0h,x0l,x1h,x1h,x1l,1,1]
__device__ __forceinline__ void write_ext(char* e, int m, float x0, float x1){
    float x0h,x0l,x1h,x1l;
    split_hl(x0, x0h, x0l); split_hl(x1, x1h, x1l);
    uint4 v = make_uint4(pack_f16(x0h, x0h), pack_f16(x0l, x1h),
                         pack_f16(x1h, x1l), pack_f16(1.0f, 1.0f));
    *reinterpret_cast<uint4*>(e + m * 16) = v;
}

// ---- one 16-row m-tile: gates GEMM + ext term (raw fp32 accumulators, NO pack) ----
__device__ __forceinline__ void mma_tile(float d[4][4], u32 ah_u, const char* extr,
                                         const Bregs& B, int mt8, int lrow, int lcol,
                                         int g, int q){
#pragma unroll
    for (int nt = 0; nt < 4; nt++)
#pragma unroll
        for (int p = 0; p < 4; p++) d[nt][p] = 0.0f;
#pragma unroll
    for (int kt = 0; kt < 4; kt++){
        u32 a[4];
        ldmA(a, ah_u + (u32)((mt8 * 16 + lrow) * STRIDE + kt * 32 + lcol));
#pragma unroll
        for (int nt = 0; nt < 4; nt++) mma16816(d[nt], a, B.bh[kt][nt]);
    }
    const int row = mt8 * 16 + g;
    u32 ae[2];
    ae[0] = *(const u32*)(extr + row * 16 + q * 4);
    ae[1] = *(const u32*)(extr + (row + 8) * 16 + q * 4);
#pragma unroll
    for (int nt = 0; nt < 4; nt++) mma1688(d[nt], ae, B.be[nt]);
}

// ---- pack fp32 gate accumulators to half2 (deferred past the previous epilogue) ----
__device__ __forceinline__ void pack_tile(u32 pg[4][2], const float d[4][4]){
#pragma unroll
    for (int nt = 0; nt < 4; nt++){
        pg[nt][0] = pack_f16(d[nt][0], d[nt][1]);
        pg[nt][1] = pack_f16(d[nt][2], d[nt][3]);
    }
}

// ---- deferred epilogue: all-half2 activations + c update + packed h STS ----
__device__ __forceinline__ void epi_tile(const u32 pg[4][2], __half2 c2[2],
                                         char* ahw, int rowA, int col){
    const __half2 H05 = __floats2half2_rn(0.5f, 0.5f);
#pragma unroll
    for (int pr = 0; pr < 2; pr++){
        u32 ti = tanh2u(pg[0][pr]);
        u32 tf = tanh2u(pg[1][pr]);
        u32 tg = tanh2u(pg[2][pr]);
        u32 to = tanh2u(pg[3][pr]);
        __half2 si = __hfma2(u2h(ti), H05, H05);
        __half2 sf = __hfma2(u2h(tf), H05, H05);
        __half2 so = __hfma2(u2h(to), H05, H05);
        __half2 cc = __hfma2(sf, c2[pr], __hmul2(si, u2h(tg)));
        c2[pr] = cc;
        u32 tc = tanh2u(h2u(cc));
        __half2 hv = __hmul2(so, u2h(tc));
        *(u32*)(ahw + (rowA + pr * 8) * STRIDE + col) = h2u(hv);
    }
}

__global__ void __launch_bounds__(NT, 2)
lstm_hmma_kernel(const float* __restrict__ in,
                 const float* __restrict__ Wih_e, const float* __restrict__ Whh_e,
                 const float* __restrict__ bih_e, const float* __restrict__ bhh_e,
                 const float* __restrict__ Wih_d, const float* __restrict__ Whh_d,
                 const float* __restrict__ bih_d, const float* __restrict__ bhh_d,
                 const float* __restrict__ Wfc,   const float* __restrict__ bfc,
                 float* __restrict__ out)
{
    extern __shared__ char smc[];
    const int tid = threadIdx.x;
    const int lane = tid & 31, w = tid >> 5;
    const int q = lane & 3, g = lane >> 2;
    const int base = blockIdx.x * EPB;
    const u32 sb = smem_u32(smc);
    float2* wfc = (float2*)(smc + SM_WFC);

    const int lrow = lane & 15;
    const int lcol = (lane >> 4) * 16;
    const int col  = w * 16 + q * 4;

    // ---- init smem ----
    if (tid < 64) wfc[tid] = make_float2(Wfc[tid], Wfc[64 + tid]);
    {
        u32* z = (u32*)(smc + SM_AH);
        for (int i = tid; i < 2 * PL / 4; i += NT) z[i] = 0u;   // h0 = 0
    }
    const float* inrow = in + (size_t)(base + tid) * (TIN * 2);  // valid for tid < EPB
    if (tid < EPB){
        float2 xv = *(const float2*)(inrow);
        write_ext(smc + SM_EXT, tid, xv.x, xv.y);
    }
    Bregs B;
    load_B(B, Whh_e, Wih_e, bih_e, bhh_e, w, g, q);
    __half2 c2[16];
#pragma unroll
    for (int i = 0; i < 16; i++) c2[i] = __floats2half2_rn(0.0f, 0.0f);
    const float bfc0 = bfc[0], bfc1 = bfc[1];
    __syncthreads();

    for (int t = 0; t < TSTEPS; t++){
        const int rb = t & 1, wbuf = rb ^ 1;
        const u32 ah_u = sb + SM_AH + rb * PL;       // read plane (fp16 h)
        char* ahw = smc + SM_AH + wbuf * PL;          // write plane
        const char* extr = smc + SM_EXT + rb * 2048;
        char* extw = smc + SM_EXT + wbuf * 2048;
        const bool dec = (t >= TIN);

        // prefetch next encoder x at step start: hides LDG latency behind the tile loop
        float2 xnext;
        if (!dec && tid < EPB){
            const int xi = (t + 1 < TIN) ? t + 1 : TIN - 1;   // t=127 -> x_127 = dec_in0
            xnext = *(const float2*)(inrow + (size_t)xi * 2);
        }

        // ---- software-pipelined 8 m-tiles: MMA(i) -> epi(i-1) -> pack(i) ----
        // pack(i) (which stalls on tile-i HMMA drain) is deferred past epi(i-1)'s
        // independent MUFU burst, keeping the tensor pipe fed during activations.
        float d[4][4];
        u32 pg[4][2];
        mma_tile(d, ah_u, extr, B, 0, lrow, lcol, g, q);
        pack_tile(pg, d);
#pragma unroll
        for (int mt8 = 1; mt8 < 8; mt8++){
            mma_tile(d, ah_u, extr, B, mt8, lrow, lcol, g, q);
            epi_tile(pg, c2 + (mt8 - 1) * 2, ahw, (mt8 - 1) * 16 + g, col);
            pack_tile(pg, d);
        }
        epi_tile(pg, c2 + 14, ahw, 7 * 16 + g, col);

        if (!dec){
            if (tid < EPB) write_ext(extw, tid, xnext.x, xnext.y);
            __syncthreads();
            if (t == TIN - 1) load_B(B, Whh_d, Wih_d, bih_d, bhh_d, w, g, q);
        } else {
            __syncthreads();                        // h_t plane complete
            // FC head: 2 threads per element, 32 dims each
            const int m = tid >> 1, half = tid & 1;
            const char* hp = ahw + m * STRIDE + half * 64;
            float p0 = 0.f, p1 = 0.f;
#pragma unroll
            for (int j = 0; j < 16; j++){
                u32 hh = *(const u32*)(hp + j * 4);
                __half2 hb = u2h(hh);
                float h0 = __half2float(hb.x);
                float h1 = __half2float(hb.y);
                const int k = half * 32 + j * 2;
                float2 wf0 = wfc[k], wf1 = wfc[k + 1];
                p0 += h0 * wf0.x + h1 * wf1.x;
                p1 += h0 * wf0.y + h1 * wf1.y;
            }
            p0 += __shfl_xor_sync(0xffffffffu, p0, 1);
            p1 += __shfl_xor_sync(0xffffffffu, p1, 1);
            if (half == 0){
                float s0 = fmaf(tanh_hw(0.5f * (p0 + bfc0)), 0.5f, 0.5f);
                float s1 = fmaf(tanh_hw(0.5f * (p1 + bfc1)), 0.5f, 0.5f);
                *(float2*)(out + (size_t)(base + m) * (TOUT * 2) + (size_t)(t - TIN) * 2)
                    = make_float2(s0, s1);
                if (t < TSTEPS - 1) write_ext(extw, m, s0, s1);   // autoregressive feedback
            }
            __syncthreads();
        }
    }
}

extern "C" void kernel_launch(void* const* d_in, const int* in_sizes, int n_in,
                              void* d_out, int out_size) {
    (void)n_in; (void)out_size;
    const float* in    = (const float*)d_in[0];
    const float* Wih_e = (const float*)d_in[1];
    const float* Whh_e = (const float*)d_in[2];
    const float* bih_e = (const float*)d_in[3];
    const float* bhh_e = (const float*)d_in[4];
    const float* Wih_d = (const float*)d_in[5];
    const float* Whh_d = (const float*)d_in[6];
    const float* bih_d = (const float*)d_in[7];
    const float* bhh_d = (const float*)d_in[8];
    const float* Wfc   = (const float*)d_in[9];
    const float* bfc   = (const float*)d_in[10];
    float* out = (float*)d_out;

    int B = in_sizes[0] / (TIN * 2);          // 131072
    int grid = B / EPB;                        // 1024 CTAs

    cudaFuncSetAttribute(lstm_hmma_kernel,
                         cudaFuncAttributeMaxDynamicSharedMemorySize, SM_TOTAL);
    lstm_hmma_kernel<<<grid, NT, SM_TOTAL>>>(
        in, Wih_e, Whh_e, bih_e, bhh_e,
        Wih_d, Whh_d, bih_d, bhh_d, Wfc, bfc, out);
}

// round 12
// speedup vs baseline: 1.0164x; 1.0164x over previous
#include <cuda_runtime.h>
#include <cuda_fp16.h>
#include <cstdint>

typedef uint32_t u32;

#define TIN 128
#define TOUT 50
#define TSTEPS 178
#define NT 256
#define EPB 128                 // batch elements per CTA

#define STRIDE 144              // h-plane row stride (bytes): 16B-aligned rows (ldmatrix), conflict-free
#define PL (128 * STRIDE)       // one h plane = 18432 B
#define SM_WFC 0                // 64 float2 = 512 B
#define SM_EXT 512              // 2 buffers x 128 rows x 16 B = 4096
#define SM_AH  4608             // 2 x PL (h fp16 planes, double buffered)
#define SM_TOTAL (SM_AH + 2 * PL)   // 41472 B  (x2 CTAs = 83 KB/SM)

// ---------- primitives ----------
__device__ __forceinline__ float tanh_hw(float x){
    float r; asm("tanh.approx.f32 %0,%1;" : "=f"(r) : "f"(x)); return r;
}
__device__ __forceinline__ u32 tanh2u(u32 x){           // two tanh in one MUFU op
    u32 r; asm("tanh.approx.f16x2 %0,%1;" : "=r"(r) : "r"(x)); return r;
}
__device__ __forceinline__ u32 smem_u32(const void* p){
    u32 a; asm("{.reg .u64 t; cvta.to.shared.u64 t, %1; cvt.u32.u64 %0, t;}" : "=r"(a) : "l"(p));
    return a;
}
__device__ __forceinline__ u32 pack_f16(float a, float b){
    __half2 v = __floats2half2_rn(a, b);
    return *reinterpret_cast<u32*>(&v);
}
__device__ __forceinline__ __half2 u2h(u32 x){ return *reinterpret_cast<__half2*>(&x); }
__device__ __forceinline__ u32 h2u(__half2 x){ return *reinterpret_cast<u32*>(&x); }
__device__ __forceinline__ void split_hl(float v, float& hi, float& lo){
    hi = __half2float(__float2half_rn(v));
    lo = v - hi;
}

// mma.sync f16 with F16 ACCUMULATORS (sm_80+ PTX): D = 2x f16x2 regs.
// Layout: d0 = (row g, cols 2q,2q+1), d1 = (row g+8, cols 2q,2q+1) — directly
// consumable by the f16x2 epilogue, no pack stage.
__device__ __forceinline__ void mma16816h(u32 d[2], const u32 a[4], const u32 b[2]){
    asm("mma.sync.aligned.m16n8k16.row.col.f16.f16.f16.f16 "
        "{%0,%1},{%2,%3,%4,%5},{%6,%7},{%0,%1};"
        : "+r"(d[0]), "+r"(d[1])
        : "r"(a[0]), "r"(a[1]), "r"(a[2]), "r"(a[3]), "r"(b[0]), "r"(b[1]));
}
__device__ __forceinline__ void mma1688h(u32 d[2], const u32 a[2], u32 b){
    asm("mma.sync.aligned.m16n8k8.row.col.f16.f16.f16.f16 "
        "{%0,%1},{%2,%3},{%4},{%0,%1};"
        : "+r"(d[0]), "+r"(d[1])
        : "r"(a[0]), "r"(a[1]), "r"(b));
}
__device__ __forceinline__ void ldmA(u32 a[4], u32 addr){
    asm volatile("ldmatrix.sync.aligned.m8n8.x4.shared.b16 {%0,%1,%2,%3}, [%4];"
                 : "=r"(a[0]), "=r"(a[1]), "=r"(a[2]), "=r"(a[3]) : "r"(addr));
}

// ---------- per-thread weight registers ----------
// warp w owns hidden dims 8w..8w+7; thread (g=lane>>2,q=lane&3): B col n = nt*64 + w*8 + g.
// fp16 single-term Whh; gates i,f,o (nt!=2) prescaled by 0.5 for tanh-based sigmoid.
struct Bregs { u32 bh[4][4][2]; u32 be[4]; };

__device__ void load_B(Bregs& B, const float* __restrict__ Whh, const float* __restrict__ Wih,
                       const float* __restrict__ bih, const float* __restrict__ bhh,
                       int w, int g, int q){
#pragma unroll
    for (int nt = 0; nt < 4; nt++){
        const float sc = (nt == 2) ? 1.0f : 0.5f;
        const int n = nt * 64 + w * 8 + g;
        const float* row = Whh + n * 64;
#pragma unroll
        for (int kt = 0; kt < 4; kt++){
            const int k0 = kt * 16 + 2 * q;
            B.bh[kt][nt][0] = pack_f16(row[k0]     * sc, row[k0 + 1] * sc);
            B.bh[kt][nt][1] = pack_f16(row[k0 + 8] * sc, row[k0 + 9] * sc);
        }
        // ext B rows: [W0h, W0l, W0h, W1h, W1l, W1h, bh, bl] (pairs with A_ext cols)
        float W0h,W0l,W1h,W1l,bsh,bsl;
        split_hl(Wih[n * 2]     * sc, W0h, W0l);
        split_hl(Wih[n * 2 + 1] * sc, W1h, W1l);
        split_hl((bih[n] + bhh[n]) * sc, bsh, bsl);
        u32 be;
        if      (q == 0) be = pack_f16(W0h, W0l);
        else if (q == 1) be = pack_f16(W0h, W1h);
        else if (q == 2) be = pack_f16(W1l, W1h);
        else             be = pack_f16(bsh, bsl);
        B.be[nt] = be;
    }
}

// A_ext row m (16B): cols [x0h,x0h,x0l,x1h,x1h,x1l,1,1]
__device__ __forceinline__ void write_ext(char* e, int m, float x0, float x1){
    float x0h,x0l,x1h,x1l;
    split_hl(x0, x0h, x0l); split_hl(x1, x1h, x1l);
    uint4 v = make_uint4(pack_f16(x0h, x0h), pack_f16(x0l, x1h),
                         pack_f16(x1h, x1l), pack_f16(1.0f, 1.0f));
    *reinterpret_cast<uint4*>(e + m * 16) = v;
}

// ---- one 16-row m-tile: gates GEMM + ext term; D = packed f16x2, ready for epilogue ----
__device__ __forceinline__ void mma_tile(u32 pg[4][2], u32 ah_u, const char* extr,
                                         const Bregs& B, int mt8, int lrow, int lcol,
                                         int g, int q){
#pragma unroll
    for (int nt = 0; nt < 4; nt++){ pg[nt][0] = 0u; pg[nt][1] = 0u; }
    const int row = mt8 * 16 + g;
    u32 ae[2];
    ae[0] = *(const u32*)(extr + row * 16 + q * 4);
    ae[1] = *(const u32*)(extr + (row + 8) * 16 + q * 4);
#pragma unroll
    for (int nt = 0; nt < 4; nt++) mma1688h(pg[nt], ae, B.be[nt]);
#pragma unroll
    for (int kt = 0; kt < 4; kt++){
        u32 a[4];
        ldmA(a, ah_u + (u32)((mt8 * 16 + lrow) * STRIDE + kt * 32 + lcol));
#pragma unroll
        for (int nt = 0; nt < 4; nt++) mma16816h(pg[nt], a, B.bh[kt][nt]);
    }
}

// ---- deferred epilogue: all-half2 activations + c update + packed h STS ----
__device__ __forceinline__ void epi_tile(const u32 pg[4][2], __half2 c2[2],
                                         char* ahw, int rowA, int col){
    const __half2 H05 = __floats2half2_rn(0.5f, 0.5f);
#pragma unroll
    for (int pr = 0; pr < 2; pr++){
        u32 ti = tanh2u(pg[0][pr]);
        u32 tf = tanh2u(pg[1][pr]);
        u32 tg = tanh2u(pg[2][pr]);
        u32 to = tanh2u(pg[3][pr]);
        __half2 si = __hfma2(u2h(ti), H05, H05);
        __half2 sf = __hfma2(u2h(tf), H05, H05);
        __half2 so = __hfma2(u2h(to), H05, H05);
        __half2 cc = __hfma2(sf, c2[pr], __hmul2(si, u2h(tg)));
        c2[pr] = cc;
        u32 tc = tanh2u(h2u(cc));
        __half2 hv = __hmul2(so, u2h(tc));
        *(u32*)(ahw + (rowA + pr * 8) * STRIDE + col) = h2u(hv);
    }
}

__global__ void __launch_bounds__(NT, 2)
lstm_hmma_kernel(const float* __restrict__ in,
                 const float* __restrict__ Wih_e, const float* __restrict__ Whh_e,
                 const float* __restrict__ bih_e, const float* __restrict__ bhh_e,
                 const float* __restrict__ Wih_d, const float* __restrict__ Whh_d,
                 const float* __restrict__ bih_d, const float* __restrict__ bhh_d,
                 const float* __restrict__ Wfc,   const float* __restrict__ bfc,
                 float* __restrict__ out)
{
    extern __shared__ char smc[];
    const int tid = threadIdx.x;
    const int lane = tid & 31, w = tid >> 5;
    const int q = lane & 3, g = lane >> 2;
    const int base = blockIdx.x * EPB;
    const u32 sb = smem_u32(smc);
    float2* wfc = (float2*)(smc + SM_WFC);

    const int lrow = lane & 15;
    const int lcol = (lane >> 4) * 16;
    const int col  = w * 16 + q * 4;

    // ---- init smem ----
    if (tid < 64) wfc[tid] = make_float2(Wfc[tid], Wfc[64 + tid]);
    {
        u32* z = (u32*)(smc + SM_AH);
        for (int i = tid; i < 2 * PL / 4; i += NT) z[i] = 0u;   // h0 = 0
    }
    const float* inrow = in + (size_t)(base + tid) * (TIN * 2);  // valid for tid < EPB
    if (tid < EPB){
        float2 xv = *(const float2*)(inrow);
        write_ext(smc + SM_EXT, tid, xv.x, xv.y);
    }
    Bregs B;
    load_B(B, Whh_e, Wih_e, bih_e, bhh_e, w, g, q);
    __half2 c2[16];
#pragma unroll
    for (int i = 0; i < 16; i++) c2[i] = __floats2half2_rn(0.0f, 0.0f);
    const float bfc0 = bfc[0], bfc1 = bfc[1];
    __syncthreads();

    for (int t = 0; t < TSTEPS; t++){
        const int rb = t & 1, wbuf = rb ^ 1;
        const u32 ah_u = sb + SM_AH + rb * PL;       // read plane (fp16 h)
        char* ahw = smc + SM_AH + wbuf * PL;          // write plane
        const char* extr = smc + SM_EXT + rb * 2048;
        char* extw = smc + SM_EXT + wbuf * 2048;
        const bool dec = (t >= TIN);

        // prefetch next encoder x at step start: hides LDG latency behind the tile loop
        float2 xnext;
        if (!dec && tid < EPB){
            const int xi = (t + 1 < TIN) ? t + 1 : TIN - 1;   // t=127 -> x_127 = dec_in0
            xnext = *(const float2*)(inrow + (size_t)xi * 2);
        }

        // ---- software-pipelined 8 m-tiles: MMA(i) overlaps epilogue(i-1) ----
        u32 pg[2][4][2];
        mma_tile(pg[0], ah_u, extr, B, 0, lrow, lcol, g, q);
#pragma unroll
        for (int mt8 = 1; mt8 < 8; mt8++){
            mma_tile(pg[mt8 & 1], ah_u, extr, B, mt8, lrow, lcol, g, q);
            epi_tile(pg[(mt8 - 1) & 1], c2 + (mt8 - 1) * 2, ahw, (mt8 - 1) * 16 + g, col);
        }
        epi_tile(pg[1], c2 + 14, ahw, 7 * 16 + g, col);

        if (!dec){
            if (tid < EPB) write_ext(extw, tid, xnext.x, xnext.y);
            __syncthreads();
            if (t == TIN - 1) load_B(B, Whh_d, Wih_d, bih_d, bhh_d, w, g, q);
        } else {
            __syncthreads();                        // h_t plane complete
            // FC head: 2 threads per element, 32 dims each
            const int m = tid >> 1, half = tid & 1;
            const char* hp = ahw + m * STRIDE + half * 64;
            float p0 = 0.f, p1 = 0.f;
#pragma unroll
            for (int j = 0; j < 16; j++){
                u32 hh = *(const u32*)(hp + j * 4);
                __half2 hb = u2h(hh);
                float h0 = __half2float(hb.x);
                float h1 = __half2float(hb.y);
                const int k = half * 32 + j * 2;
                float2 wf0 = wfc[k], wf1 = wfc[k + 1];
                p0 += h0 * wf0.x + h1 * wf1.x;
                p1 += h0 * wf0.y + h1 * wf1.y;
            }
            p0 += __shfl_xor_sync(0xffffffffu, p0, 1);
            p1 += __shfl_xor_sync(0xffffffffu, p1, 1);
            if (half == 0){
                float s0 = fmaf(tanh_hw(0.5f * (p0 + bfc0)), 0.5f, 0.5f);
                float s1 = fmaf(tanh_hw(0.5f * (p1 + bfc1)), 0.5f, 0.5f);
                *(float2*)(out + (size_t)(base + m) * (TOUT * 2) + (size_t)(t - TIN) * 2)
                    = make_float2(s0, s1);
                if (t < TSTEPS - 1) write_ext(extw, m, s0, s1);   // autoregressive feedback
            }
            __syncthreads();
        }
    }
}

extern "C" void kernel_launch(void* const* d_in, const int* in_sizes, int n_in,
                              void* d_out, int out_size) {
    (void)n_in; (void)out_size;
    const float* in    = (const float*)d_in[0];
    const float* Wih_e = (const float*)d_in[1];
    const float* Whh_e = (const float*)d_in[2];
    const float* bih_e = (const float*)d_in[3];
    const float* bhh_e = (const float*)d_in[4];
    const float* Wih_d = (const float*)d_in[5];
    const float* Whh_d = (const float*)d_in[6];
    const float* bih_d = (const float*)d_in[7];
    const float* bhh_d = (const float*)d_in[8];
    const float* Wfc   = (const float*)d_in[9];
    const float* bfc   = (const float*)d_in[10];
    float* out = (float*)d_out;

    int B = in_sizes[0] / (TIN * 2);          // 131072
    int grid = B / EPB;                        // 1024 CTAs

    cudaFuncSetAttribute(lstm_hmma_kernel,
                         cudaFuncAttributeMaxDynamicSharedMemorySize, SM_TOTAL);
    lstm_hmma_kernel<<<grid, NT, SM_TOTAL>>>(
        in, Wih_e, Whh_e, bih_e, bhh_e,
        Wih_d, Whh_d, bih_d, bhh_d, Wfc, bfc, out);
}

// round 13
// speedup vs baseline: 1.0955x; 1.0778x over previous
#include <cuda_runtime.h>
#include <cuda_fp16.h>
#include <cstdint>

typedef uint32_t u32;

#define TIN 128
#define TOUT 50
#define TSTEPS 178
#define NT 256
#define EPB 128                 // batch elements per CTA

#define STRIDE 144              // h-plane row stride (bytes): 16B-aligned rows (ldmatrix), conflict-free
#define PL (128 * STRIDE)       // one h plane = 18432 B
#define SM_WFC 0                // 64 float2 = 512 B
#define SM_EXT 512              // 2 buffers x 128 rows x 16 B = 4096
#define SM_AH  4608             // 2 x PL (h fp16 planes, double buffered)
#define SM_TOTAL (SM_AH + 2 * PL)   // 41472 B  (x2 CTAs = 83 KB/SM)

// ---------- primitives ----------
__device__ __forceinline__ float tanh_hw(float x){
    float r; asm("tanh.approx.f32 %0,%1;" : "=f"(r) : "f"(x)); return r;
}
// VOLATILE: participates in the pinned interleave schedule
__device__ __forceinline__ u32 tanh2u(u32 x){
    u32 r; asm volatile("tanh.approx.f16x2 %0,%1;" : "=r"(r) : "r"(x)); return r;
}
__device__ __forceinline__ u32 smem_u32(const void* p){
    u32 a; asm("{.reg .u64 t; cvta.to.shared.u64 t, %1; cvt.u32.u64 %0, t;}" : "=r"(a) : "l"(p));
    return a;
}
__device__ __forceinline__ u32 pack_f16(float a, float b){
    __half2 v = __floats2half2_rn(a, b);
    return *reinterpret_cast<u32*>(&v);
}
__device__ __forceinline__ __half2 u2h(u32 x){ return *reinterpret_cast<__half2*>(&x); }
__device__ __forceinline__ u32 h2u(__half2 x){ return *reinterpret_cast<u32*>(&x); }
__device__ __forceinline__ void split_hl(float v, float& hi, float& lo){
    hi = __half2float(__float2half_rn(v));
    lo = v - hi;
}

// mma.sync f16, F16 accumulators. VOLATILE: pins issue order so MUFU ops woven
// between HMMA groups actually issue there (fills tensor-queue-full stall slots).
__device__ __forceinline__ void mma16816h(u32 d[2], const u32 a[4], const u32 b[2]){
    asm volatile("mma.sync.aligned.m16n8k16.row.col.f16.f16.f16.f16 "
        "{%0,%1},{%2,%3,%4,%5},{%6,%7},{%0,%1};"
        : "+r"(d[0]), "+r"(d[1])
        : "r"(a[0]), "r"(a[1]), "r"(a[2]), "r"(a[3]), "r"(b[0]), "r"(b[1]));
}
__device__ __forceinline__ void mma1688h(u32 d[2], const u32 a[2], u32 b){
    asm volatile("mma.sync.aligned.m16n8k8.row.col.f16.f16.f16.f16 "
        "{%0,%1},{%2,%3},{%4},{%0,%1};"
        : "+r"(d[0]), "+r"(d[1])
        : "r"(a[0]), "r"(a[1]), "r"(b));
}
__device__ __forceinline__ void ldmA(u32 a[4], u32 addr){
    asm volatile("ldmatrix.sync.aligned.m8n8.x4.shared.b16 {%0,%1,%2,%3}, [%4];"
                 : "=r"(a[0]), "=r"(a[1]), "=r"(a[2]), "=r"(a[3]) : "r"(addr));
}

// ---------- per-thread weight registers ----------
struct Bregs { u32 bh[4][4][2]; u32 be[4]; };

__device__ void load_B(Bregs& B, const float* __restrict__ Whh, const float* __restrict__ Wih,
                       const float* __restrict__ bih, const float* __restrict__ bhh,
                       int w, int g, int q){
#pragma unroll
    for (int nt = 0; nt < 4; nt++){
        const float sc = (nt == 2) ? 1.0f : 0.5f;
        const int n = nt * 64 + w * 8 + g;
        const float* row = Whh + n * 64;
#pragma unroll
        for (int kt = 0; kt < 4; kt++){
            const int k0 = kt * 16 + 2 * q;
            B.bh[kt][nt][0] = pack_f16(row[k0]     * sc, row[k0 + 1] * sc);
            B.bh[kt][nt][1] = pack_f16(row[k0 + 8] * sc, row[k0 + 9] * sc);
        }
        float W0h,W0l,W1h,W1l,bsh,bsl;
        split_hl(Wih[n * 2]     * sc, W0h, W0l);
        split_hl(Wih[n * 2 + 1] * sc, W1h, W1l);
        split_hl((bih[n] + bhh[n]) * sc, bsh, bsl);
        u32 be;
        if      (q == 0) be = pack_f16(W0h, W0l);
        else if (q == 1) be = pack_f16(W0h, W1h);
        else if (q == 2) be = pack_f16(W1l, W1h);
        else             be = pack_f16(bsh, bsl);
        B.be[nt] = be;
    }
}

// A_ext row m (16B): cols [x0h,x0h,x0l,x1h,x1h,x1l,1,1]
__device__ __forceinline__ void write_ext(char* e, int m, float x0, float x1){
    float x0h,x0l,x1h,x1l;
    split_hl(x0, x0h, x0l); split_hl(x1, x1h, x1l);
    uint4 v = make_uint4(pack_f16(x0h, x0h), pack_f16(x0l, x1h),
                         pack_f16(x1h, x1l), pack_f16(1.0f, 1.0f));
    *reinterpret_cast<uint4*>(e + m * 16) = v;
}

// ---- plain MMA tile (prologue: no pending epilogue to weave) ----
__device__ __forceinline__ void mma_tile(u32 pg[4][2], u32 ah_u, const char* extr,
                                         const Bregs& B, int mt8, int lrow, int lcol,
                                         int g, int q){
#pragma unroll
    for (int nt = 0; nt < 4; nt++){ pg[nt][0] = 0u; pg[nt][1] = 0u; }
    const int row = mt8 * 16 + g;
    u32 ae[2];
    ae[0] = *(const u32*)(extr + row * 16 + q * 4);
    ae[1] = *(const u32*)(extr + (row + 8) * 16 + q * 4);
#pragma unroll
    for (int nt = 0; nt < 4; nt++) mma1688h(pg[nt], ae, B.be[nt]);
#pragma unroll
    for (int kt = 0; kt < 4; kt++){
        u32 a[4];
        ldmA(a, ah_u + (u32)((mt8 * 16 + lrow) * STRIDE + kt * 32 + lcol));
#pragma unroll
        for (int nt = 0; nt < 4; nt++) mma16816h(pg[nt], a, B.bh[kt][nt]);
    }
}

// ---- plain epilogue tile (tail: no MMA to weave) ----
__device__ __forceinline__ void epi_tile(const u32 pg[4][2], __half2 c2[2],
                                         char* ahw, int rowA, int col){
    const __half2 H05 = __floats2half2_rn(0.5f, 0.5f);
#pragma unroll
    for (int pr = 0; pr < 2; pr++){
        u32 ti = tanh2u(pg[0][pr]);
        u32 tf = tanh2u(pg[1][pr]);
        u32 tg = tanh2u(pg[2][pr]);
        u32 to = tanh2u(pg[3][pr]);
        __half2 si = __hfma2(u2h(ti), H05, H05);
        __half2 sf = __hfma2(u2h(tf), H05, H05);
        __half2 so = __hfma2(u2h(to), H05, H05);
        __half2 cc = __hfma2(sf, c2[pr], __hmul2(si, u2h(tg)));
        c2[pr] = cc;
        u32 tc = tanh2u(h2u(cc));
        __half2 hv = __hmul2(so, u2h(tc));
        *(u32*)(ahw + (rowA + pr * 8) * STRIDE + col) = h2u(hv);
    }
}

// ---- fused tile: MMA(cur) with epi(prev) hand-woven between HMMA groups.
// All mma/tanh are volatile, so this source order IS the issue order: each
// 4-HMMA group is followed by MUFU work that fills the tensor-queue drain.
__device__ __forceinline__ void tile_fused(u32 pgc[4][2], const u32 pgp[4][2],
                                           __half2 c2p[2], char* ahw, int rowAp, int col,
                                           u32 ah_u, const char* extr, const Bregs& B,
                                           int mt8, int lrow, int lcol, int g, int q){
    const __half2 H05 = __floats2half2_rn(0.5f, 0.5f);
#pragma unroll
    for (int nt = 0; nt < 4; nt++){ pgc[nt][0] = 0u; pgc[nt][1] = 0u; }
    const u32 abase = ah_u + (u32)((mt8 * 16 + lrow) * STRIDE + lcol);
    u32 a[4];

    // ---- kt0 ----
    ldmA(a, abase);
    mma16816h(pgc[0], a, B.bh[0][0]); mma16816h(pgc[1], a, B.bh[0][1]);
    mma16816h(pgc[2], a, B.bh[0][2]); mma16816h(pgc[3], a, B.bh[0][3]);
    u32 ti0 = tanh2u(pgp[0][0]);
    u32 tf0 = tanh2u(pgp[1][0]);
    u32 tg0 = tanh2u(pgp[2][0]);
    u32 to0 = tanh2u(pgp[3][0]);

    // ---- kt1 ----
    ldmA(a, abase + 32);
    mma16816h(pgc[0], a, B.bh[1][0]); mma16816h(pgc[1], a, B.bh[1][1]);
    mma16816h(pgc[2], a, B.bh[1][2]); mma16816h(pgc[3], a, B.bh[1][3]);
    __half2 si0 = __hfma2(u2h(ti0), H05, H05);
    __half2 sf0 = __hfma2(u2h(tf0), H05, H05);
    __half2 so0 = __hfma2(u2h(to0), H05, H05);
    __half2 cc0 = __hfma2(sf0, c2p[0], __hmul2(si0, u2h(tg0)));
    c2p[0] = cc0;
    u32 tc0 = tanh2u(h2u(cc0));

    // ---- kt2 ----
    ldmA(a, abase + 64);
    mma16816h(pgc[0], a, B.bh[2][0]); mma16816h(pgc[1], a, B.bh[2][1]);
    mma16816h(pgc[2], a, B.bh[2][2]); mma16816h(pgc[3], a, B.bh[2][3]);
    __half2 hv0 = __hmul2(so0, u2h(tc0));
    *(u32*)(ahw + rowAp * STRIDE + col) = h2u(hv0);
    u32 ti1 = tanh2u(pgp[0][1]);
    u32 tf1 = tanh2u(pgp[1][1]);
    u32 tg1 = tanh2u(pgp[2][1]);

    // ---- kt3 ----
    ldmA(a, abase + 96);
    mma16816h(pgc[0], a, B.bh[3][0]); mma16816h(pgc[1], a, B.bh[3][1]);
    mma16816h(pgc[2], a, B.bh[3][2]); mma16816h(pgc[3], a, B.bh[3][3]);
    u32 to1 = tanh2u(pgp[3][1]);
    __half2 si1 = __hfma2(u2h(ti1), H05, H05);
    __half2 sf1 = __hfma2(u2h(tf1), H05, H05);
    __half2 so1 = __hfma2(u2h(to1), H05, H05);
    __half2 cc1 = __hfma2(sf1, c2p[1], __hmul2(si1, u2h(tg1)));
    c2p[1] = cc1;

    // ---- ext (K=8) ----
    {
        const int row = mt8 * 16 + g;
        u32 ae[2];
        ae[0] = *(const u32*)(extr + row * 16 + q * 4);
        ae[1] = *(const u32*)(extr + (row + 8) * 16 + q * 4);
        mma1688h(pgc[0], ae, B.be[0]); mma1688h(pgc[1], ae, B.be[1]);
        mma1688h(pgc[2], ae, B.be[2]); mma1688h(pgc[3], ae, B.be[3]);
    }
    u32 tc1 = tanh2u(h2u(cc1));
    __half2 hv1 = __hmul2(so1, u2h(tc1));
    *(u32*)(ahw + (rowAp + 8) * STRIDE + col) = h2u(hv1);
}

__global__ void __launch_bounds__(NT, 2)
lstm_hmma_kernel(const float* __restrict__ in,
                 const float* __restrict__ Wih_e, const float* __restrict__ Whh_e,
                 const float* __restrict__ bih_e, const float* __restrict__ bhh_e,
                 const float* __restrict__ Wih_d, const float* __restrict__ Whh_d,
                 const float* __restrict__ bih_d, const float* __restrict__ bhh_d,
                 const float* __restrict__ Wfc,   const float* __restrict__ bfc,
                 float* __restrict__ out)
{
    extern __shared__ char smc[];
    const int tid = threadIdx.x;
    const int lane = tid & 31, w = tid >> 5;
    const int q = lane & 3, g = lane >> 2;
    const int base = blockIdx.x * EPB;
    const u32 sb = smem_u32(smc);
    float2* wfc = (float2*)(smc + SM_WFC);

    const int lrow = lane & 15;
    const int lcol = (lane >> 4) * 16;
    const int col  = w * 16 + q * 4;

    // ---- init smem ----
    if (tid < 64) wfc[tid] = make_float2(Wfc[tid], Wfc[64 + tid]);
    {
        u32* z = (u32*)(smc + SM_AH);
        for (int i = tid; i < 2 * PL / 4; i += NT) z[i] = 0u;   // h0 = 0
    }
    const float* inrow = in + (size_t)(base + tid) * (TIN * 2);  // valid for tid < EPB
    if (tid < EPB){
        float2 xv = *(const float2*)(inrow);
        write_ext(smc + SM_EXT, tid, xv.x, xv.y);
    }
    Bregs B;
    load_B(B, Whh_e, Wih_e, bih_e, bhh_e, w, g, q);
    __half2 c2[16];
#pragma unroll
    for (int i = 0; i < 16; i++) c2[i] = __floats2half2_rn(0.0f, 0.0f);
    const float bfc0 = bfc[0], bfc1 = bfc[1];
    __syncthreads();

    for (int t = 0; t < TSTEPS; t++){
        const int rb = t & 1, wbuf = rb ^ 1;
        const u32 ah_u = sb + SM_AH + rb * PL;       // read plane (fp16 h)
        char* ahw = smc + SM_AH + wbuf * PL;          // write plane
        const char* extr = smc + SM_EXT + rb * 2048;
        char* extw = smc + SM_EXT + wbuf * 2048;
        const bool dec = (t >= TIN);

        // prefetch next encoder x at step start
        float2 xnext;
        if (!dec && tid < EPB){
            const int xi = (t + 1 < TIN) ? t + 1 : TIN - 1;   // t=127 -> x_127 = dec_in0
            xnext = *(const float2*)(inrow + (size_t)xi * 2);
        }

        // ---- pipelined 8 m-tiles, epilogue woven inside the MMA bursts ----
        u32 pg[2][4][2];
        mma_tile(pg[0], ah_u, extr, B, 0, lrow, lcol, g, q);
#pragma unroll
        for (int mt8 = 1; mt8 < 8; mt8++){
            tile_fused(pg[mt8 & 1], pg[(mt8 - 1) & 1], c2 + (mt8 - 1) * 2,
                       ahw, (mt8 - 1) * 16 + g, col,
                       ah_u, extr, B, mt8, lrow, lcol, g, q);
        }
        epi_tile(pg[1], c2 + 14, ahw, 7 * 16 + g, col);

        if (!dec){
            if (tid < EPB) write_ext(extw, tid, xnext.x, xnext.y);
            __syncthreads();
            if (t == TIN - 1) load_B(B, Whh_d, Wih_d, bih_d, bhh_d, w, g, q);
        } else {
            __syncthreads();                        // h_t plane complete
            // FC head: 2 threads per element, 32 dims each
            const int m = tid >> 1, half = tid & 1;
            const char* hp = ahw + m * STRIDE + half * 64;
            float p0 = 0.f, p1 = 0.f;
#pragma unroll
            for (int j = 0; j < 16; j++){
                u32 hh = *(const u32*)(hp + j * 4);
                __half2 hb = u2h(hh);
                float h0 = __half2float(hb.x);
                float h1 = __half2float(hb.y);
                const int k = half * 32 + j * 2;
                float2 wf0 = wfc[k], wf1 = wfc[k + 1];
                p0 += h0 * wf0.x + h1 * wf1.x;
                p1 += h0 * wf0.y + h1 * wf1.y;
            }
            p0 += __shfl_xor_sync(0xffffffffu, p0, 1);
            p1 += __shfl_xor_sync(0xffffffffu, p1, 1);
            if (half == 0){
                float s0 = fmaf(tanh_hw(0.5f * (p0 + bfc0)), 0.5f, 0.5f);
                float s1 = fmaf(tanh_hw(0.5f * (p1 + bfc1)), 0.5f, 0.5f);
                *(float2*)(out + (size_t)(base + m) * (TOUT * 2) + (size_t)(t - TIN) * 2)
                    = make_float2(s0, s1);
                if (t < TSTEPS - 1) write_ext(extw, m, s0, s1);   // autoregressive feedback
            }
            __syncthreads();
        }
    }
}

extern "C" void kernel_launch(void* const* d_in, const int* in_sizes, int n_in,
                              void* d_out, int out_size) {
    (void)n_in; (void)out_size;
    const float* in    = (const float*)d_in[0];
    const float* Wih_e = (const float*)d_in[1];
    const float* Whh_e = (const float*)d_in[2];
    const float* bih_e = (const float*)d_in[3];
    const float* bhh_e = (const float*)d_in[4];
    const float* Wih_d = (const float*)d_in[5];
    const float* Whh_d = (const float*)d_in[6];
    const float* bih_d = (const float*)d_in[7];
    const float* bhh_d = (const float*)d_in[8];
    const float* Wfc   = (const float*)d_in[9];
    const float* bfc   = (const float*)d_in[10];
    float* out = (float*)d_out;

    int B = in_sizes[0] / (TIN * 2);          // 131072
    int grid = B / EPB;                        // 1024 CTAs

    cudaFuncSetAttribute(lstm_hmma_kernel,
                         cudaFuncAttributeMaxDynamicSharedMemorySize, SM_TOTAL);
    lstm_hmma_kernel<<<grid, NT, SM_TOTAL>>>(
        in, Wih_e, Whh_e, bih_e, bhh_e,
        Wih_d, Whh_d, bih_d, bhh_d, Wfc, bfc, out);
}